// round 16
// baseline (speedup 1.0000x reference)
#include <cuda_runtime.h>
#include <cuda_fp16.h>
#include <math.h>
#include <stdint.h>

#define BATCH 2
#define SEQ   2048
#define DIM   1024
#define NH    16
#define HD    64
#define M_TOT (BATCH*SEQ)           // 4096
#define SCALE_Q 0.18033688011112042f  // 0.125 * log2(e): scores in log2 domain

// ---- scratch (device globals; 16B-aligned for cp.async) ----
__device__ __align__(16) __half g_aq[(size_t)M_TOT*DIM];
__device__ __align__(16) __half g_ak[(size_t)M_TOT*DIM];
__device__ __align__(16) __half g_av[(size_t)M_TOT*DIM];
__device__ __align__(16) __half g_wq[(size_t)NH*HD*DIM];   // [h][e][k] (transposed)
__device__ __align__(16) __half g_wk[(size_t)NH*HD*DIM];
__device__ __align__(16) __half g_wv[(size_t)NH*HD*DIM];
__device__ __align__(16) __half g_wo[(size_t)DIM*DIM];     // [n][k] (transposed)
__device__ __align__(16) __half g_q [(size_t)BATCH*NH*SEQ*HD]; // [bh][s][e], pre-scaled
__device__ __align__(16) __half g_k [(size_t)BATCH*NH*SEQ*HD]; // [bh][s][e]
__device__ __align__(16) __half g_vT[(size_t)BATCH*NH*HD*SEQ]; // [bh][e][s]
__device__ __align__(16) __half g_ctx[(size_t)M_TOT*DIM];      // [b][s][h*HD+e]

// ---- helpers ----
__device__ __forceinline__ uint32_t smem_u32(const void* p) {
    return (uint32_t)__cvta_generic_to_shared(p);
}
__device__ __forceinline__ uint32_t packh2(float a, float b) {
    __half2 h = __floats2half2_rn(a, b);
    return *(uint32_t*)&h;
}
__device__ __forceinline__ uint32_t ex2h2(uint32_t x) {
    uint32_t y; asm("ex2.approx.f16x2 %0, %1;" : "=r"(y) : "r"(x)); return y;
}
#define CP_ASYNC16(dst, src) \
    asm volatile("cp.async.cg.shared.global [%0], [%1], 16;" :: "r"(dst), "l"(src))
#define CP_COMMIT() asm volatile("cp.async.commit_group;")
#define CP_WAIT0()  asm volatile("cp.async.wait_group 0;")
#define CP_WAIT1()  asm volatile("cp.async.wait_group 1;")

// D += A(16x16) * B(16x8), fp16 inputs, fp32 accum.
__device__ __forceinline__ void mma_f16(float* d, const uint32_t* a, const uint32_t* b) {
    asm volatile(
        "mma.sync.aligned.m16n8k16.row.col.f32.f16.f16.f32 "
        "{%0,%1,%2,%3}, {%4,%5,%6,%7}, {%8,%9}, {%0,%1,%2,%3};"
        : "+f"(d[0]), "+f"(d[1]), "+f"(d[2]), "+f"(d[3])
        : "r"(a[0]), "r"(a[1]), "r"(a[2]), "r"(a[3]), "r"(b[0]), "r"(b[1]));
}
// ldmatrix x4: 4 8x8 half matrices; lanes 0-7/8-15/16-23/24-31 supply row addrs.
__device__ __forceinline__ void ldsm_x4(uint32_t* r, uint32_t addr) {
    asm volatile("ldmatrix.sync.aligned.m8n8.x4.shared.b16 {%0,%1,%2,%3}, [%4];"
        : "=r"(r[0]), "=r"(r[1]), "=r"(r[2]), "=r"(r[3]) : "r"(addr));
}

// 64-half rows (32 words), 128B XOR swizzle. Returns half index of word start.
__device__ __forceinline__ int idx64(int r, int wc) {
    return r * 64 + ((wc ^ ((r & 7) << 2)) << 1);
}

// ---------------------------------------------------------------------------
// Prep
// ---------------------------------------------------------------------------
__global__ __launch_bounds__(256) void prep_act_kernel(
    const float* __restrict__ q, const float* __restrict__ k, const float* __restrict__ v)
{
    const int z = blockIdx.y;
    const float4* s = (const float4*)(z == 0 ? q : z == 1 ? k : v);
    __half* d = (z == 0 ? g_aq : z == 1 ? g_ak : g_av);
    const size_t i = (size_t)blockIdx.x * 256 + threadIdx.x;
    float4 x = s[i];
    __half2* dp = (__half2*)(d + i * 4);
    dp[0] = __floats2half2_rn(x.x, x.y);
    dp[1] = __floats2half2_rn(x.z, x.w);
}

// Transpose + convert the 3 per-head weight stacks in ONE launch (z = 48).
__global__ __launch_bounds__(256) void prep_wT3_kernel(
    const float* __restrict__ wq, const float* __restrict__ wk, const float* __restrict__ wv)
{
    __shared__ float tile[32][33];
    const int which = blockIdx.z >> 4;
    const int b = blockIdx.z & 15;
    const float* src = which == 0 ? wq : which == 1 ? wk : wv;
    __half* dst = which == 0 ? g_wq : which == 1 ? g_wk : g_wv;
    const int k0 = blockIdx.x * 32, e0 = blockIdx.y * 32;
    const int tx = threadIdx.x & 31, ty = threadIdx.x >> 5;
    const float* s = src + (size_t)b * DIM * HD;
    __half* d = dst + (size_t)b * DIM * HD;
    #pragma unroll
    for (int j = 0; j < 32; j += 8)
        tile[ty + j][tx] = s[(size_t)(k0 + ty + j) * HD + e0 + tx];
    __syncthreads();
    #pragma unroll
    for (int j = 0; j < 32; j += 8)
        d[(size_t)(e0 + ty + j) * DIM + k0 + tx] = __float2half_rn(tile[tx][ty + j]);
}

__global__ __launch_bounds__(256) void prep_wT_kernel(
    const float* __restrict__ src, __half* __restrict__ dst, int K, int E)
{
    __shared__ float tile[32][33];
    const int k0 = blockIdx.x * 32, e0 = blockIdx.y * 32;
    const int tx = threadIdx.x & 31, ty = threadIdx.x >> 5;
    #pragma unroll
    for (int j = 0; j < 32; j += 8)
        tile[ty + j][tx] = src[(size_t)(k0 + ty + j) * E + e0 + tx];
    __syncthreads();
    #pragma unroll
    for (int j = 0; j < 32; j += 8)
        dst[(size_t)(e0 + ty + j) * K + k0 + tx] = __float2half_rn(tile[tx][ty + j]);
}

// ---------------------------------------------------------------------------
// GEMM: BM=128, BN=128, BK=64, 256 threads (8 warps: 4m x 2n), double-buffered,
// 2 CTAs/SM, single barrier per iteration. Fragments via ldmatrix.x4.
// ---------------------------------------------------------------------------
#define GS_A (128*64)
#define GS_B (128*64)
#define G_STAGE_H (GS_A + GS_B)            // 16384 halves
#define GEMM_SMEM (2*G_STAGE_H*2)          // 65,536 B

__global__ __launch_bounds__(256, 2) void qkv_mma_kernel(
    const float* __restrict__ bq, const float* __restrict__ bk, const float* __restrict__ bv)
{
    extern __shared__ __half smh[];
    const int which = blockIdx.z;
    const __half* A    = which == 0 ? g_aq : which == 1 ? g_ak : g_av;
    const __half* W    = which == 0 ? g_wq : which == 1 ? g_wk : g_wv;
    const float* bias  = which == 0 ? bq   : which == 1 ? bk   : bv;

    const int m0 = blockIdx.x * 128;
    const int hp = blockIdx.y;
    const int t = threadIdx.x;
    const int warp = t >> 5, lane = t & 31, g = lane >> 2, tg = lane & 3;
    const int wm = (warp >> 1) * 32, wn = (warp & 1) * 64;

    const int ln_base  = ((lane >> 4) << 3) + (lane & 7);
    const int lwc_base = ((lane >> 3) & 1) << 2;
    const int la_row   = (((lane >> 3) & 1) << 3) + (lane & 7);
    const int la_wc    = (lane >> 4) << 2;

    const __half* WbT = W + (size_t)(hp * 2) * HD * DIM;

    auto issue = [&](int k0, int st) {
        __half* As = smh + st * G_STAGE_H;
        __half* Bs = As + GS_A;
        #pragma unroll
        for (int j = 0; j < 4; j++) {
            const int lin = j * 256 + t;
            const int r = lin >> 3, c = lin & 7;
            CP_ASYNC16(smem_u32(&As[idx64(r, c * 4)]),
                       &A[(size_t)(m0 + r) * DIM + k0 + c * 8]);
        }
        #pragma unroll
        for (int j = 0; j < 4; j++) {
            const int lin = j * 256 + t;
            const int n = lin >> 3, c = lin & 7;
            CP_ASYNC16(smem_u32(&Bs[idx64(n, c * 4)]),
                       &WbT[(size_t)n * DIM + k0 + c * 8]);
        }
    };

    float acc[2][8][4];
    #pragma unroll
    for (int i = 0; i < 2; i++)
        #pragma unroll
        for (int j = 0; j < 8; j++)
            #pragma unroll
            for (int c = 0; c < 4; c++) acc[i][j][c] = 0.f;

    issue(0, 0); CP_COMMIT();
    for (int it = 0; it < DIM / 64; it++) {
        CP_WAIT0(); __syncthreads();   // single barrier: also orders stage reuse
        if (it < DIM / 64 - 1) { issue((it + 1) * 64, (it + 1) & 1); CP_COMMIT(); }
        const __half* As = smh + (it & 1) * G_STAGE_H;
        const __half* Bs = As + GS_A;
        #pragma unroll
        for (int kk = 0; kk < 4; kk++) {
            uint32_t bf[8][2];
            #pragma unroll
            for (int j = 0; j < 4; j++) {
                const int n = wn + j * 16 + ln_base;
                ldsm_x4(&bf[2 * j][0],
                        smem_u32(&Bs[idx64(n, kk * 8 + lwc_base)]));
            }
            uint32_t af[2][4];
            #pragma unroll
            for (int mf = 0; mf < 2; mf++)
                ldsm_x4(af[mf],
                        smem_u32(&As[idx64(wm + mf * 16 + la_row, kk * 8 + la_wc)]));
            #pragma unroll
            for (int mf = 0; mf < 2; mf++)
                #pragma unroll
                for (int nf = 0; nf < 8; nf++)
                    mma_f16(acc[mf][nf], af[mf], bf[nf]);
        }
    }

    const int h = hp * 2 + (wn >> 6);
    float2 bl[8];
    #pragma unroll
    for (int nf = 0; nf < 8; nf++)
        bl[nf] = *(const float2*)&bias[h * HD + nf * 8 + 2 * tg];

    #pragma unroll
    for (int mf = 0; mf < 2; mf++) {
        #pragma unroll
        for (int half_ = 0; half_ < 2; half_++) {
            const int m = m0 + wm + mf * 16 + g + half_ * 8;
            const int b = m >> 11, s = m & (SEQ - 1);
            const int bh = b * NH + h;
            if (which == 0) {
                __half* dst = g_q + ((size_t)bh * SEQ + s) * HD;
                #pragma unroll
                for (int nf = 0; nf < 8; nf++)
                    *(__half2*)&dst[nf * 8 + 2 * tg] = __floats2half2_rn(
                        (acc[mf][nf][half_*2+0] + bl[nf].x) * SCALE_Q,
                        (acc[mf][nf][half_*2+1] + bl[nf].y) * SCALE_Q);
            } else if (which == 1) {
                __half* dst = g_k + ((size_t)bh * SEQ + s) * HD;
                #pragma unroll
                for (int nf = 0; nf < 8; nf++)
                    *(__half2*)&dst[nf * 8 + 2 * tg] = __floats2half2_rn(
                        acc[mf][nf][half_*2+0] + bl[nf].x,
                        acc[mf][nf][half_*2+1] + bl[nf].y);
            } else {
                const size_t base = (size_t)bh * HD * SEQ;
                #pragma unroll
                for (int nf = 0; nf < 8; nf++) {
                    const int e = nf * 8 + 2 * tg;
                    g_vT[base + (size_t)(e    ) * SEQ + s] = __float2half_rn(acc[mf][nf][half_*2+0] + bl[nf].x);
                    g_vT[base + (size_t)(e + 1) * SEQ + s] = __float2half_rn(acc[mf][nf][half_*2+1] + bl[nf].y);
                }
            }
        }
    }
}

__global__ __launch_bounds__(256, 2) void out_mma_kernel(
    const float* __restrict__ bo, float* __restrict__ out)
{
    extern __shared__ __half smh[];
    const int m0 = blockIdx.x * 128;
    const int n0 = blockIdx.y * 128;
    const int t = threadIdx.x;
    const int warp = t >> 5, lane = t & 31, g = lane >> 2, tg = lane & 3;
    const int wm = (warp >> 1) * 32, wn = (warp & 1) * 64;

    const int ln_base  = ((lane >> 4) << 3) + (lane & 7);
    const int lwc_base = ((lane >> 3) & 1) << 2;
    const int la_row   = (((lane >> 3) & 1) << 3) + (lane & 7);
    const int la_wc    = (lane >> 4) << 2;

    auto issue = [&](int k0, int st) {
        __half* As = smh + st * G_STAGE_H;
        __half* Bs = As + GS_A;
        #pragma unroll
        for (int j = 0; j < 4; j++) {
            const int lin = j * 256 + t;
            const int r = lin >> 3, c = lin & 7;
            CP_ASYNC16(smem_u32(&As[idx64(r, c * 4)]),
                       &g_ctx[(size_t)(m0 + r) * DIM + k0 + c * 8]);
        }
        #pragma unroll
        for (int j = 0; j < 4; j++) {
            const int lin = j * 256 + t;
            const int n = lin >> 3, c = lin & 7;
            CP_ASYNC16(smem_u32(&Bs[idx64(n, c * 4)]),
                       &g_wo[(size_t)(n0 + n) * DIM + k0 + c * 8]);
        }
    };

    float acc[2][8][4];
    #pragma unroll
    for (int i = 0; i < 2; i++)
        #pragma unroll
        for (int j = 0; j < 8; j++)
            #pragma unroll
            for (int c = 0; c < 4; c++) acc[i][j][c] = 0.f;

    issue(0, 0); CP_COMMIT();
    for (int it = 0; it < DIM / 64; it++) {
        CP_WAIT0(); __syncthreads();
        if (it < DIM / 64 - 1) { issue((it + 1) * 64, (it + 1) & 1); CP_COMMIT(); }
        const __half* As = smh + (it & 1) * G_STAGE_H;
        const __half* Bs = As + GS_A;
        #pragma unroll
        for (int kk = 0; kk < 4; kk++) {
            uint32_t bf[8][2];
            #pragma unroll
            for (int j = 0; j < 4; j++) {
                const int n = wn + j * 16 + ln_base;
                ldsm_x4(&bf[2 * j][0],
                        smem_u32(&Bs[idx64(n, kk * 8 + lwc_base)]));
            }
            uint32_t af[2][4];
            #pragma unroll
            for (int mf = 0; mf < 2; mf++)
                ldsm_x4(af[mf],
                        smem_u32(&As[idx64(wm + mf * 16 + la_row, kk * 8 + la_wc)]));
            #pragma unroll
            for (int mf = 0; mf < 2; mf++)
                #pragma unroll
                for (int nf = 0; nf < 8; nf++)
                    mma_f16(acc[mf][nf], af[mf], bf[nf]);
        }
    }

    float2 bl[8];
    #pragma unroll
    for (int nf = 0; nf < 8; nf++)
        bl[nf] = *(const float2*)&bo[n0 + wn + nf * 8 + 2 * tg];

    #pragma unroll
    for (int mf = 0; mf < 2; mf++) {
        #pragma unroll
        for (int half_ = 0; half_ < 2; half_++) {
            const int m = m0 + wm + mf * 16 + g + half_ * 8;
            float* dst = out + (size_t)m * DIM + n0 + wn;
            #pragma unroll
            for (int nf = 0; nf < 8; nf++) {
                float2 o;
                o.x = acc[mf][nf][half_*2+0] + bl[nf].x;
                o.y = acc[mf][nf][half_*2+1] + bl[nf].y;
                *(float2*)&dst[nf * 8 + 2 * tg] = o;
            }
        }
    }
}

// ---------------------------------------------------------------------------
// Flash attention: Q-tile 128, KV 64, 256 threads, 2 CTAs/SM, 3-STAGE pipeline.
// B-fragments via ldmatrix.x4. P in registers; exp via ex2.f16x2; l via ones-MMA.
// ---------------------------------------------------------------------------
#define F_STAGE_H  (2*64*64)                // K + Vt per stage (16KB)
#define FLASH_SMEM (3*F_STAGE_H*2)          // 49,152 B
#define ONES_H2 0x3C003C00u                 // half2(1.0, 1.0)
#define NTILE (SEQ/64)                      // 32

__global__ __launch_bounds__(256, 2) void flash_mma_kernel(const int* __restrict__ mask)
{
    extern __shared__ __half smh[];
    __half* KV = smh;               // 3 stages x (Ks [64][64] + Vt [64][64])

    const int bh = blockIdx.y;
    const int b = bh >> 4, h = bh & 15;
    const int q0 = blockIdx.x * 128;
    const int t = threadIdx.x;
    const int warp = t >> 5, lane = t & 31, g = lane >> 2, tg = lane & 3;
    const int wm = warp * 16;

    const int ln_base  = ((lane >> 4) << 3) + (lane & 7);
    const int lwc_base = ((lane >> 3) & 1) << 2;

    const __half* qp  = g_q  + ((size_t)bh * SEQ + q0) * HD;
    const __half* kp  = g_k  + (size_t)bh * SEQ * HD;
    const __half* vTp = g_vT + (size_t)bh * HD * SEQ;
    const int*    mp  = mask + (size_t)b * SEQ;

    // ---- Stage Q once through stage-0 area; hoist fragments to registers ----
    {
        __half* Qs = KV;
        #pragma unroll
        for (int j = 0; j < 4; j++) {
            const int lin = j * 256 + t;
            const int r = lin >> 3, c = lin & 7;
            CP_ASYNC16(smem_u32(&Qs[idx64(r, c * 4)]),
                       &qp[(size_t)r * HD + c * 8]);
        }
        CP_COMMIT(); CP_WAIT0();
        __syncthreads();
    }
    uint32_t qf[4][4];
    {
        const __half* Qs = KV;
        const int la_row = (((lane >> 3) & 1) << 3) + (lane & 7);
        const int la_wc  = (lane >> 4) << 2;
        #pragma unroll
        for (int kk = 0; kk < 4; kk++)
            ldsm_x4(qf[kk], smem_u32(&Qs[idx64(wm + la_row, kk * 8 + la_wc)]));
        __syncthreads();   // all reads done before KV prologue overwrites
    }

    auto issue_kv = [&](int kv0, int st) {
        __half* Ks = KV + st * F_STAGE_H;
        __half* Vt = Ks + 64 * 64;
        #pragma unroll
        for (int j = 0; j < 2; j++) {
            const int lin = j * 256 + t;
            const int r = lin >> 3, c = lin & 7;
            CP_ASYNC16(smem_u32(&Ks[idx64(r, c * 4)]),
                       &kp[(size_t)(kv0 + r) * HD + c * 8]);
        }
        #pragma unroll
        for (int j = 0; j < 2; j++) {
            const int lin = j * 256 + t;
            const int r = lin >> 3, c = lin & 7;
            CP_ASYNC16(smem_u32(&Vt[idx64(r, c * 4)]),
                       &vTp[(size_t)r * SEQ + kv0 + c * 8]);
        }
    };

    issue_kv(0, 0); CP_COMMIT();
    issue_kv(64, 1); CP_COMMIT();

    float ctx[8][4];
    #pragma unroll
    for (int j = 0; j < 8; j++)
        #pragma unroll
        for (int c = 0; c < 4; c++) ctx[j][c] = 0.f;
    float lacc[4] = {0.f, 0.f, 0.f, 0.f};
    const uint32_t ones_bf[2] = {ONES_H2, ONES_H2};

    int st = 0, st2 = 2;   // current stage, stage for it+2
    for (int it = 0; it < NTILE; it++) {
        if (it + 1 < NTILE) { CP_WAIT1(); } else { CP_WAIT0(); }
        __syncthreads();
        if (it + 2 < NTILE) { issue_kv((it + 2) * 64, st2); CP_COMMIT(); }
        const __half* Ks = KV + st * F_STAGE_H;
        const __half* Vt = Ks + 64 * 64;

        // --- S = Q . K^T (log2 domain); B-frags via ldmatrix.x4 ---
        float sacc[8][4];
        #pragma unroll
        for (int j = 0; j < 8; j++)
            #pragma unroll
            for (int c = 0; c < 4; c++) sacc[j][c] = 0.f;

        #pragma unroll
        for (int kk = 0; kk < 4; kk++) {
            uint32_t bf[8][2];
            #pragma unroll
            for (int j = 0; j < 4; j++) {
                const int n = j * 16 + ln_base;
                ldsm_x4(&bf[2 * j][0],
                        smem_u32(&Ks[idx64(n, kk * 8 + lwc_base)]));
            }
            #pragma unroll
            for (int nf = 0; nf < 8; nf++)
                mma_f16(sacc[nf], qf[kk], bf[nf]);
        }

        // --- mask -> cvt-to-half2 -> ex2.f16x2 (result IS the PV A-frag) ---
        const int kvb = it * 64;
        uint32_t pf[4][4];
        #pragma unroll
        for (int nf = 0; nf < 8; nf++) {
            const int2 mv = *(const int2*)&mp[kvb + nf * 8 + 2 * tg];
            if (!mv.x) { sacc[nf][0] = -1e9f; sacc[nf][2] = -1e9f; }   // cvt -> -inf
            if (!mv.y) { sacc[nf][1] = -1e9f; sacc[nf][3] = -1e9f; }
            pf[nf >> 1][(nf & 1) * 2 + 0] = ex2h2(packh2(sacc[nf][0], sacc[nf][1]));
            pf[nf >> 1][(nf & 1) * 2 + 1] = ex2h2(packh2(sacc[nf][2], sacc[nf][3]));
        }

        // --- ctx += P . V ; l += P . 1 ---
        #pragma unroll
        for (int kk = 0; kk < 4; kk++) {
            uint32_t bf[8][2];
            #pragma unroll
            for (int j = 0; j < 4; j++) {
                const int n = j * 16 + ln_base;
                ldsm_x4(&bf[2 * j][0],
                        smem_u32(&Vt[idx64(n, kk * 8 + lwc_base)]));
            }
            #pragma unroll
            for (int nf = 0; nf < 8; nf++)
                mma_f16(ctx[nf], pf[kk], bf[nf]);
            mma_f16(lacc, pf[kk], ones_bf);
        }

        st  = (st  == 2) ? 0 : st  + 1;
        st2 = (st2 == 2) ? 0 : st2 + 1;
    }

    // epilogue: lacc[0]=row g sum, lacc[2]=row g+8 sum (all cols identical)
    #pragma unroll
    for (int half_ = 0; half_ < 2; half_++) {
        const float l = lacc[half_ * 2];
        const float inv = (l > 0.f) ? 1.f / l : 0.f;
        const int q = q0 + wm + g + half_ * 8;
        __half* dst = &g_ctx[((size_t)b * SEQ + q) * DIM + h * HD];
        #pragma unroll
        for (int nf = 0; nf < 8; nf++)
            *(__half2*)&dst[nf * 8 + 2 * tg] = __floats2half2_rn(
                ctx[nf][half_*2+0] * inv, ctx[nf][half_*2+1] * inv);
    }
}

// ---------------------------------------------------------------------------
extern "C" void kernel_launch(void* const* d_in, const int* in_sizes, int n_in,
                              void* d_out, int out_size)
{
    (void)in_sizes; (void)n_in; (void)out_size;
    const float* query = (const float*)d_in[0];
    const float* key   = (const float*)d_in[1];
    const float* value = (const float*)d_in[2];
    const int*   mask  = (const int*)d_in[3];
    const float* Wq = (const float*)d_in[4];
    const float* bq = (const float*)d_in[5];
    const float* Wk = (const float*)d_in[6];
    const float* bk = (const float*)d_in[7];
    const float* Wv = (const float*)d_in[8];
    const float* bv = (const float*)d_in[9];
    const float* Wo = (const float*)d_in[10];
    const float* bo = (const float*)d_in[11];
    float* out = (float*)d_out;

    cudaFuncSetAttribute(qkv_mma_kernel, cudaFuncAttributeMaxDynamicSharedMemorySize, GEMM_SMEM);
    cudaFuncSetAttribute(out_mma_kernel, cudaFuncAttributeMaxDynamicSharedMemorySize, GEMM_SMEM);
    cudaFuncSetAttribute(flash_mma_kernel, cudaFuncAttributeMaxDynamicSharedMemorySize, FLASH_SMEM);

    prep_act_kernel<<<dim3(4096, 3), 256>>>(query, key, value);
    prep_wT3_kernel<<<dim3(32, 2, 48), 256>>>(Wq, Wk, Wv);

    __half* d_wo;
    cudaGetSymbolAddress((void**)&d_wo, g_wo);
    prep_wT_kernel<<<dim3(32, 32, 1), 256>>>(Wo, d_wo, DIM, DIM);

    dim3 gQKV(M_TOT / 128, NH / 2, 3);
    qkv_mma_kernel<<<gQKV, 256, GEMM_SMEM>>>(bq, bk, bv);

    dim3 gFA(SEQ / 128, BATCH * NH);
    flash_mma_kernel<<<gFA, 256, FLASH_SMEM>>>(mask);

    dim3 gOUT(M_TOT / 128, DIM / 128);
    out_mma_kernel<<<gOUT, 256, GEMM_SMEM>>>(bo, out);
}

// round 17
// speedup vs baseline: 1.0175x; 1.0175x over previous
#include <cuda_runtime.h>
#include <cuda_fp16.h>
#include <math.h>
#include <stdint.h>

#define BATCH 2
#define SEQ   2048
#define DIM   1024
#define NH    16
#define HD    64
#define M_TOT (BATCH*SEQ)           // 4096
#define SCALE_Q 0.18033688011112042f  // 0.125 * log2(e): scores in log2 domain

// ---- scratch (device globals; 16B-aligned for cp.async) ----
__device__ __align__(16) __half g_aq[(size_t)M_TOT*DIM];
__device__ __align__(16) __half g_ak[(size_t)M_TOT*DIM];
__device__ __align__(16) __half g_av[(size_t)M_TOT*DIM];
__device__ __align__(16) __half g_wq[(size_t)NH*HD*DIM];   // [h][e][k] (transposed)
__device__ __align__(16) __half g_wk[(size_t)NH*HD*DIM];
__device__ __align__(16) __half g_wv[(size_t)NH*HD*DIM];
__device__ __align__(16) __half g_wo[(size_t)DIM*DIM];     // [n][k] (transposed)
__device__ __align__(16) __half g_q [(size_t)BATCH*NH*SEQ*HD]; // [bh][s][e], pre-scaled
__device__ __align__(16) __half g_k [(size_t)BATCH*NH*SEQ*HD]; // [bh][s][e]
__device__ __align__(16) __half g_vT[(size_t)BATCH*NH*HD*SEQ]; // [bh][e][s]
__device__ __align__(16) __half g_ctx[(size_t)M_TOT*DIM];      // [b][s][h*HD+e]

// ---- helpers ----
__device__ __forceinline__ uint32_t smem_u32(const void* p) {
    return (uint32_t)__cvta_generic_to_shared(p);
}
__device__ __forceinline__ uint32_t packh2(float a, float b) {
    __half2 h = __floats2half2_rn(a, b);
    return *(uint32_t*)&h;
}
__device__ __forceinline__ uint32_t ex2h2(uint32_t x) {
    uint32_t y; asm("ex2.approx.f16x2 %0, %1;" : "=r"(y) : "r"(x)); return y;
}
#define CP_ASYNC16(dst, src) \
    asm volatile("cp.async.cg.shared.global [%0], [%1], 16;" :: "r"(dst), "l"(src))
#define CP_COMMIT() asm volatile("cp.async.commit_group;")
#define CP_WAIT0()  asm volatile("cp.async.wait_group 0;")
#define CP_WAIT1()  asm volatile("cp.async.wait_group 1;")

// D += A(16x16) * B(16x8), fp16 inputs, fp32 accum.
__device__ __forceinline__ void mma_f16(float* d, const uint32_t* a, const uint32_t* b) {
    asm volatile(
        "mma.sync.aligned.m16n8k16.row.col.f32.f16.f16.f32 "
        "{%0,%1,%2,%3}, {%4,%5,%6,%7}, {%8,%9}, {%0,%1,%2,%3};"
        : "+f"(d[0]), "+f"(d[1]), "+f"(d[2]), "+f"(d[3])
        : "r"(a[0]), "r"(a[1]), "r"(a[2]), "r"(a[3]), "r"(b[0]), "r"(b[1]));
}
// ldmatrix x4: 4 8x8 half matrices; lanes 0-7/8-15/16-23/24-31 supply row addrs.
__device__ __forceinline__ void ldsm_x4(uint32_t* r, uint32_t addr) {
    asm volatile("ldmatrix.sync.aligned.m8n8.x4.shared.b16 {%0,%1,%2,%3}, [%4];"
        : "=r"(r[0]), "=r"(r[1]), "=r"(r[2]), "=r"(r[3]) : "r"(addr));
}

// 64-half rows (32 words), 128B XOR swizzle. Returns half index of word start.
__device__ __forceinline__ int idx64(int r, int wc) {
    return r * 64 + ((wc ^ ((r & 7) << 2)) << 1);
}

// ---------------------------------------------------------------------------
// Prep
// ---------------------------------------------------------------------------
__global__ __launch_bounds__(256) void prep_act_kernel(
    const float* __restrict__ q, const float* __restrict__ k, const float* __restrict__ v)
{
    const int z = blockIdx.y;
    const float4* s = (const float4*)(z == 0 ? q : z == 1 ? k : v);
    __half* d = (z == 0 ? g_aq : z == 1 ? g_ak : g_av);
    const size_t i = (size_t)blockIdx.x * 256 + threadIdx.x;
    float4 x = s[i];
    __half2* dp = (__half2*)(d + i * 4);
    dp[0] = __floats2half2_rn(x.x, x.y);
    dp[1] = __floats2half2_rn(x.z, x.w);
}

// Transpose + convert the 3 per-head weight stacks in ONE launch (z = 48).
__global__ __launch_bounds__(256) void prep_wT3_kernel(
    const float* __restrict__ wq, const float* __restrict__ wk, const float* __restrict__ wv)
{
    __shared__ float tile[32][33];
    const int which = blockIdx.z >> 4;
    const int b = blockIdx.z & 15;
    const float* src = which == 0 ? wq : which == 1 ? wk : wv;
    __half* dst = which == 0 ? g_wq : which == 1 ? g_wk : g_wv;
    const int k0 = blockIdx.x * 32, e0 = blockIdx.y * 32;
    const int tx = threadIdx.x & 31, ty = threadIdx.x >> 5;
    const float* s = src + (size_t)b * DIM * HD;
    __half* d = dst + (size_t)b * DIM * HD;
    #pragma unroll
    for (int j = 0; j < 32; j += 8)
        tile[ty + j][tx] = s[(size_t)(k0 + ty + j) * HD + e0 + tx];
    __syncthreads();
    #pragma unroll
    for (int j = 0; j < 32; j += 8)
        d[(size_t)(e0 + ty + j) * DIM + k0 + tx] = __float2half_rn(tile[tx][ty + j]);
}

__global__ __launch_bounds__(256) void prep_wT_kernel(
    const float* __restrict__ src, __half* __restrict__ dst, int K, int E)
{
    __shared__ float tile[32][33];
    const int k0 = blockIdx.x * 32, e0 = blockIdx.y * 32;
    const int tx = threadIdx.x & 31, ty = threadIdx.x >> 5;
    #pragma unroll
    for (int j = 0; j < 32; j += 8)
        tile[ty + j][tx] = src[(size_t)(k0 + ty + j) * E + e0 + tx];
    __syncthreads();
    #pragma unroll
    for (int j = 0; j < 32; j += 8)
        dst[(size_t)(e0 + ty + j) * K + k0 + tx] = __float2half_rn(tile[tx][ty + j]);
}

// ---------------------------------------------------------------------------
// GEMM: BM=128, BN=128, BK=64, 256 threads (8 warps: 4m x 2n), 3-STAGE
// cp.async pipeline, 2 CTAs/SM, single barrier per iteration. ldmatrix.x4.
// ---------------------------------------------------------------------------
#define GS_A (128*64)
#define GS_B (128*64)
#define G_STAGE_H (GS_A + GS_B)            // 16384 halves (32KB)
#define GEMM_SMEM (3*G_STAGE_H*2)          // 98,304 B
#define G_NIT (DIM/64)                     // 16

__global__ __launch_bounds__(256, 2) void qkv_mma_kernel(
    const float* __restrict__ bq, const float* __restrict__ bk, const float* __restrict__ bv)
{
    extern __shared__ __half smh[];
    const int which = blockIdx.z;
    const __half* A    = which == 0 ? g_aq : which == 1 ? g_ak : g_av;
    const __half* W    = which == 0 ? g_wq : which == 1 ? g_wk : g_wv;
    const float* bias  = which == 0 ? bq   : which == 1 ? bk   : bv;

    const int m0 = blockIdx.x * 128;
    const int hp = blockIdx.y;
    const int t = threadIdx.x;
    const int warp = t >> 5, lane = t & 31, g = lane >> 2, tg = lane & 3;
    const int wm = (warp >> 1) * 32, wn = (warp & 1) * 64;

    const int ln_base  = ((lane >> 4) << 3) + (lane & 7);
    const int lwc_base = ((lane >> 3) & 1) << 2;
    const int la_row   = (((lane >> 3) & 1) << 3) + (lane & 7);
    const int la_wc    = (lane >> 4) << 2;

    const __half* WbT = W + (size_t)(hp * 2) * HD * DIM;

    auto issue = [&](int k0, int st) {
        __half* As = smh + st * G_STAGE_H;
        __half* Bs = As + GS_A;
        #pragma unroll
        for (int j = 0; j < 4; j++) {
            const int lin = j * 256 + t;
            const int r = lin >> 3, c = lin & 7;
            CP_ASYNC16(smem_u32(&As[idx64(r, c * 4)]),
                       &A[(size_t)(m0 + r) * DIM + k0 + c * 8]);
        }
        #pragma unroll
        for (int j = 0; j < 4; j++) {
            const int lin = j * 256 + t;
            const int n = lin >> 3, c = lin & 7;
            CP_ASYNC16(smem_u32(&Bs[idx64(n, c * 4)]),
                       &WbT[(size_t)n * DIM + k0 + c * 8]);
        }
    };

    float acc[2][8][4];
    #pragma unroll
    for (int i = 0; i < 2; i++)
        #pragma unroll
        for (int j = 0; j < 8; j++)
            #pragma unroll
            for (int c = 0; c < 4; c++) acc[i][j][c] = 0.f;

    issue(0, 0); CP_COMMIT();
    issue(64, 1); CP_COMMIT();
    int st = 0, st2 = 2;
    for (int it = 0; it < G_NIT; it++) {
        if (it + 1 < G_NIT) { CP_WAIT1(); } else { CP_WAIT0(); }
        __syncthreads();
        if (it + 2 < G_NIT) { issue((it + 2) * 64, st2); CP_COMMIT(); }
        const __half* As = smh + st * G_STAGE_H;
        const __half* Bs = As + GS_A;
        #pragma unroll
        for (int kk = 0; kk < 4; kk++) {
            uint32_t bf[8][2];
            #pragma unroll
            for (int j = 0; j < 4; j++) {
                const int n = wn + j * 16 + ln_base;
                ldsm_x4(&bf[2 * j][0],
                        smem_u32(&Bs[idx64(n, kk * 8 + lwc_base)]));
            }
            uint32_t af[2][4];
            #pragma unroll
            for (int mf = 0; mf < 2; mf++)
                ldsm_x4(af[mf],
                        smem_u32(&As[idx64(wm + mf * 16 + la_row, kk * 8 + la_wc)]));
            #pragma unroll
            for (int mf = 0; mf < 2; mf++)
                #pragma unroll
                for (int nf = 0; nf < 8; nf++)
                    mma_f16(acc[mf][nf], af[mf], bf[nf]);
        }
        st  = (st  == 2) ? 0 : st  + 1;
        st2 = (st2 == 2) ? 0 : st2 + 1;
    }

    const int h = hp * 2 + (wn >> 6);
    float2 bl[8];
    #pragma unroll
    for (int nf = 0; nf < 8; nf++)
        bl[nf] = *(const float2*)&bias[h * HD + nf * 8 + 2 * tg];

    #pragma unroll
    for (int mf = 0; mf < 2; mf++) {
        #pragma unroll
        for (int half_ = 0; half_ < 2; half_++) {
            const int m = m0 + wm + mf * 16 + g + half_ * 8;
            const int b = m >> 11, s = m & (SEQ - 1);
            const int bh = b * NH + h;
            if (which == 0) {
                __half* dst = g_q + ((size_t)bh * SEQ + s) * HD;
                #pragma unroll
                for (int nf = 0; nf < 8; nf++)
                    *(__half2*)&dst[nf * 8 + 2 * tg] = __floats2half2_rn(
                        (acc[mf][nf][half_*2+0] + bl[nf].x) * SCALE_Q,
                        (acc[mf][nf][half_*2+1] + bl[nf].y) * SCALE_Q);
            } else if (which == 1) {
                __half* dst = g_k + ((size_t)bh * SEQ + s) * HD;
                #pragma unroll
                for (int nf = 0; nf < 8; nf++)
                    *(__half2*)&dst[nf * 8 + 2 * tg] = __floats2half2_rn(
                        acc[mf][nf][half_*2+0] + bl[nf].x,
                        acc[mf][nf][half_*2+1] + bl[nf].y);
            } else {
                const size_t base = (size_t)bh * HD * SEQ;
                #pragma unroll
                for (int nf = 0; nf < 8; nf++) {
                    const int e = nf * 8 + 2 * tg;
                    g_vT[base + (size_t)(e    ) * SEQ + s] = __float2half_rn(acc[mf][nf][half_*2+0] + bl[nf].x);
                    g_vT[base + (size_t)(e + 1) * SEQ + s] = __float2half_rn(acc[mf][nf][half_*2+1] + bl[nf].y);
                }
            }
        }
    }
}

__global__ __launch_bounds__(256, 2) void out_mma_kernel(
    const float* __restrict__ bo, float* __restrict__ out)
{
    extern __shared__ __half smh[];
    const int m0 = blockIdx.x * 128;
    const int n0 = blockIdx.y * 128;
    const int t = threadIdx.x;
    const int warp = t >> 5, lane = t & 31, g = lane >> 2, tg = lane & 3;
    const int wm = (warp >> 1) * 32, wn = (warp & 1) * 64;

    const int ln_base  = ((lane >> 4) << 3) + (lane & 7);
    const int lwc_base = ((lane >> 3) & 1) << 2;
    const int la_row   = (((lane >> 3) & 1) << 3) + (lane & 7);
    const int la_wc    = (lane >> 4) << 2;

    auto issue = [&](int k0, int st) {
        __half* As = smh + st * G_STAGE_H;
        __half* Bs = As + GS_A;
        #pragma unroll
        for (int j = 0; j < 4; j++) {
            const int lin = j * 256 + t;
            const int r = lin >> 3, c = lin & 7;
            CP_ASYNC16(smem_u32(&As[idx64(r, c * 4)]),
                       &g_ctx[(size_t)(m0 + r) * DIM + k0 + c * 8]);
        }
        #pragma unroll
        for (int j = 0; j < 4; j++) {
            const int lin = j * 256 + t;
            const int n = lin >> 3, c = lin & 7;
            CP_ASYNC16(smem_u32(&Bs[idx64(n, c * 4)]),
                       &g_wo[(size_t)(n0 + n) * DIM + k0 + c * 8]);
        }
    };

    float acc[2][8][4];
    #pragma unroll
    for (int i = 0; i < 2; i++)
        #pragma unroll
        for (int j = 0; j < 8; j++)
            #pragma unroll
            for (int c = 0; c < 4; c++) acc[i][j][c] = 0.f;

    issue(0, 0); CP_COMMIT();
    issue(64, 1); CP_COMMIT();
    int st = 0, st2 = 2;
    for (int it = 0; it < G_NIT; it++) {
        if (it + 1 < G_NIT) { CP_WAIT1(); } else { CP_WAIT0(); }
        __syncthreads();
        if (it + 2 < G_NIT) { issue((it + 2) * 64, st2); CP_COMMIT(); }
        const __half* As = smh + st * G_STAGE_H;
        const __half* Bs = As + GS_A;
        #pragma unroll
        for (int kk = 0; kk < 4; kk++) {
            uint32_t bf[8][2];
            #pragma unroll
            for (int j = 0; j < 4; j++) {
                const int n = wn + j * 16 + ln_base;
                ldsm_x4(&bf[2 * j][0],
                        smem_u32(&Bs[idx64(n, kk * 8 + lwc_base)]));
            }
            uint32_t af[2][4];
            #pragma unroll
            for (int mf = 0; mf < 2; mf++)
                ldsm_x4(af[mf],
                        smem_u32(&As[idx64(wm + mf * 16 + la_row, kk * 8 + la_wc)]));
            #pragma unroll
            for (int mf = 0; mf < 2; mf++)
                #pragma unroll
                for (int nf = 0; nf < 8; nf++)
                    mma_f16(acc[mf][nf], af[mf], bf[nf]);
        }
        st  = (st  == 2) ? 0 : st  + 1;
        st2 = (st2 == 2) ? 0 : st2 + 1;
    }

    float2 bl[8];
    #pragma unroll
    for (int nf = 0; nf < 8; nf++)
        bl[nf] = *(const float2*)&bo[n0 + wn + nf * 8 + 2 * tg];

    #pragma unroll
    for (int mf = 0; mf < 2; mf++) {
        #pragma unroll
        for (int half_ = 0; half_ < 2; half_++) {
            const int m = m0 + wm + mf * 16 + g + half_ * 8;
            float* dst = out + (size_t)m * DIM + n0 + wn;
            #pragma unroll
            for (int nf = 0; nf < 8; nf++) {
                float2 o;
                o.x = acc[mf][nf][half_*2+0] + bl[nf].x;
                o.y = acc[mf][nf][half_*2+1] + bl[nf].y;
                *(float2*)&dst[nf * 8 + 2 * tg] = o;
            }
        }
    }
}

// ---------------------------------------------------------------------------
// Flash attention (round-15 proven config): Q-tile 128, KV 64, 256 threads,
// 2 CTAs/SM, 2-stage pipeline. ldmatrix.x4 B-frags; P in registers;
// exp via ex2.f16x2; l via ones-MMA.
// ---------------------------------------------------------------------------
#define FKV_H  (2*64*64)                    // K + Vt per stage (16KB)
#define FLASH_SMEM (2*FKV_H*2)              // 32,768 B
#define ONES_H2 0x3C003C00u                 // half2(1.0, 1.0)

__global__ __launch_bounds__(256, 2) void flash_mma_kernel(const int* __restrict__ mask)
{
    extern __shared__ __half smh[];
    __half* KV = smh;               // 2 stages x (Ks [64][64] + Vt [64][64])

    const int bh = blockIdx.y;
    const int b = bh >> 4, h = bh & 15;
    const int q0 = blockIdx.x * 128;
    const int t = threadIdx.x;
    const int warp = t >> 5, lane = t & 31, g = lane >> 2, tg = lane & 3;
    const int wm = warp * 16;

    const int ln_base  = ((lane >> 4) << 3) + (lane & 7);
    const int lwc_base = ((lane >> 3) & 1) << 2;

    const __half* qp  = g_q  + ((size_t)bh * SEQ + q0) * HD;
    const __half* kp  = g_k  + (size_t)bh * SEQ * HD;
    const __half* vTp = g_vT + (size_t)bh * HD * SEQ;
    const int*    mp  = mask + (size_t)b * SEQ;

    // ---- Stage Q once through KV stage 0; hoist fragments to registers ----
    {
        __half* Qs = KV;
        #pragma unroll
        for (int j = 0; j < 4; j++) {
            const int lin = j * 256 + t;
            const int r = lin >> 3, c = lin & 7;
            CP_ASYNC16(smem_u32(&Qs[idx64(r, c * 4)]),
                       &qp[(size_t)r * HD + c * 8]);
        }
        CP_COMMIT(); CP_WAIT0();
        __syncthreads();
    }
    uint32_t qf[4][4];
    {
        const __half* Qs = KV;
        const int la_row = (((lane >> 3) & 1) << 3) + (lane & 7);
        const int la_wc  = (lane >> 4) << 2;
        #pragma unroll
        for (int kk = 0; kk < 4; kk++)
            ldsm_x4(qf[kk], smem_u32(&Qs[idx64(wm + la_row, kk * 8 + la_wc)]));
        __syncthreads();   // all reads done before KV prologue overwrites
    }

    auto issue_kv = [&](int kv0, int st) {
        __half* Ks = KV + st * FKV_H;
        __half* Vt = Ks + 64 * 64;
        #pragma unroll
        for (int j = 0; j < 2; j++) {
            const int lin = j * 256 + t;
            const int r = lin >> 3, c = lin & 7;
            CP_ASYNC16(smem_u32(&Ks[idx64(r, c * 4)]),
                       &kp[(size_t)(kv0 + r) * HD + c * 8]);
        }
        #pragma unroll
        for (int j = 0; j < 2; j++) {
            const int lin = j * 256 + t;
            const int r = lin >> 3, c = lin & 7;
            CP_ASYNC16(smem_u32(&Vt[idx64(r, c * 4)]),
                       &vTp[(size_t)r * SEQ + kv0 + c * 8]);
        }
    };

    issue_kv(0, 0); CP_COMMIT();

    float ctx[8][4];
    #pragma unroll
    for (int j = 0; j < 8; j++)
        #pragma unroll
        for (int c = 0; c < 4; c++) ctx[j][c] = 0.f;
    float lacc[4] = {0.f, 0.f, 0.f, 0.f};
    const uint32_t ones_bf[2] = {ONES_H2, ONES_H2};

    for (int it = 0; it < SEQ / 64; it++) {
        CP_WAIT0(); __syncthreads();
        if (it < SEQ / 64 - 1) { issue_kv((it + 1) * 64, (it + 1) & 1); CP_COMMIT(); }
        const __half* Ks = KV + (it & 1) * FKV_H;
        const __half* Vt = Ks + 64 * 64;

        // --- S = Q . K^T (log2 domain); B-frags via ldmatrix.x4 ---
        float sacc[8][4];
        #pragma unroll
        for (int j = 0; j < 8; j++)
            #pragma unroll
            for (int c = 0; c < 4; c++) sacc[j][c] = 0.f;

        #pragma unroll
        for (int kk = 0; kk < 4; kk++) {
            uint32_t bf[8][2];
            #pragma unroll
            for (int j = 0; j < 4; j++) {
                const int n = j * 16 + ln_base;
                ldsm_x4(&bf[2 * j][0],
                        smem_u32(&Ks[idx64(n, kk * 8 + lwc_base)]));
            }
            #pragma unroll
            for (int nf = 0; nf < 8; nf++)
                mma_f16(sacc[nf], qf[kk], bf[nf]);
        }

        // --- mask -> cvt-to-half2 -> ex2.f16x2 (result IS the PV A-frag) ---
        const int kvb = it * 64;
        uint32_t pf[4][4];
        #pragma unroll
        for (int nf = 0; nf < 8; nf++) {
            const int2 mv = *(const int2*)&mp[kvb + nf * 8 + 2 * tg];
            if (!mv.x) { sacc[nf][0] = -1e9f; sacc[nf][2] = -1e9f; }   // cvt -> -inf
            if (!mv.y) { sacc[nf][1] = -1e9f; sacc[nf][3] = -1e9f; }
            pf[nf >> 1][(nf & 1) * 2 + 0] = ex2h2(packh2(sacc[nf][0], sacc[nf][1]));
            pf[nf >> 1][(nf & 1) * 2 + 1] = ex2h2(packh2(sacc[nf][2], sacc[nf][3]));
        }

        // --- ctx += P . V ; l += P . 1 ---
        #pragma unroll
        for (int kk = 0; kk < 4; kk++) {
            uint32_t bf[8][2];
            #pragma unroll
            for (int j = 0; j < 4; j++) {
                const int n = j * 16 + ln_base;
                ldsm_x4(&bf[2 * j][0],
                        smem_u32(&Vt[idx64(n, kk * 8 + lwc_base)]));
            }
            #pragma unroll
            for (int nf = 0; nf < 8; nf++)
                mma_f16(ctx[nf], pf[kk], bf[nf]);
            mma_f16(lacc, pf[kk], ones_bf);
        }
    }

    // epilogue: lacc[0]=row g sum, lacc[2]=row g+8 sum (all cols identical)
    #pragma unroll
    for (int half_ = 0; half_ < 2; half_++) {
        const float l = lacc[half_ * 2];
        const float inv = (l > 0.f) ? 1.f / l : 0.f;
        const int q = q0 + wm + g + half_ * 8;
        __half* dst = &g_ctx[((size_t)b * SEQ + q) * DIM + h * HD];
        #pragma unroll
        for (int nf = 0; nf < 8; nf++)
            *(__half2*)&dst[nf * 8 + 2 * tg] = __floats2half2_rn(
                ctx[nf][half_*2+0] * inv, ctx[nf][half_*2+1] * inv);
    }
}

// ---------------------------------------------------------------------------
extern "C" void kernel_launch(void* const* d_in, const int* in_sizes, int n_in,
                              void* d_out, int out_size)
{
    (void)in_sizes; (void)n_in; (void)out_size;
    const float* query = (const float*)d_in[0];
    const float* key   = (const float*)d_in[1];
    const float* value = (const float*)d_in[2];
    const int*   mask  = (const int*)d_in[3];
    const float* Wq = (const float*)d_in[4];
    const float* bq = (const float*)d_in[5];
    const float* Wk = (const float*)d_in[6];
    const float* bk = (const float*)d_in[7];
    const float* Wv = (const float*)d_in[8];
    const float* bv = (const float*)d_in[9];
    const float* Wo = (const float*)d_in[10];
    const float* bo = (const float*)d_in[11];
    float* out = (float*)d_out;

    cudaFuncSetAttribute(qkv_mma_kernel, cudaFuncAttributeMaxDynamicSharedMemorySize, GEMM_SMEM);
    cudaFuncSetAttribute(out_mma_kernel, cudaFuncAttributeMaxDynamicSharedMemorySize, GEMM_SMEM);
    cudaFuncSetAttribute(flash_mma_kernel, cudaFuncAttributeMaxDynamicSharedMemorySize, FLASH_SMEM);

    prep_act_kernel<<<dim3(4096, 3), 256>>>(query, key, value);
    prep_wT3_kernel<<<dim3(32, 2, 48), 256>>>(Wq, Wk, Wv);

    __half* d_wo;
    cudaGetSymbolAddress((void**)&d_wo, g_wo);
    prep_wT_kernel<<<dim3(32, 32, 1), 256>>>(Wo, d_wo, DIM, DIM);

    dim3 gQKV(M_TOT / 128, NH / 2, 3);
    qkv_mma_kernel<<<gQKV, 256, GEMM_SMEM>>>(bq, bk, bv);

    dim3 gFA(SEQ / 128, BATCH * NH);
    flash_mma_kernel<<<gFA, 256, FLASH_SMEM>>>(mask);

    dim3 gOUT(M_TOT / 128, DIM / 128);
    out_mma_kernel<<<gOUT, 256, GEMM_SMEM>>>(bo, out);
}